// round 3
// baseline (speedup 1.0000x reference)
#include <cuda_runtime.h>
#include <cstdint>
#include <math.h>

#define Yx   256
#define TP1  513
#define Tt   512
#define MAT  (TP1 * Yx * Yx)   // 33,619,968

// ---------------- scratch (static device globals; no allocation) ----------
__device__ __align__(16) float g_Mexp[MAT];            // exp(logM), masked entries = 0
__device__ float g_alpha[(TP1 + 1) * Yx];              // normalized alpha_t, t=0..513
__device__ float g_beta [(TP1 + 1) * Yx];              // normalized beta_t,  t=0..513
__device__ float g_sA[TP1];                            // per-step forward norms
__device__ float g_sB[TP1];                            // per-step backward norms
__device__ float g_Ap[TP1 * Yx];                       // alpha_t * F[t]
__device__ __align__(16) unsigned char g_idx[(Tt - 1) * Yx]; // viterbi backptrs
__device__ float g_dfin[Yx];                           // final (scaled) delta

// ---------------- helpers -------------------------------------------------
__device__ __forceinline__ unsigned smem_u32(const void* p) {
    return (unsigned)__cvta_generic_to_shared(p);
}
__device__ __forceinline__ void stClusterF(unsigned saddr, unsigned peer, float v) {
    unsigned ra;
    asm volatile("mapa.shared::cluster.u32 %0, %1, %2;" : "=r"(ra) : "r"(saddr), "r"(peer));
    asm volatile("st.shared::cluster.f32 [%0], %1;" :: "r"(ra), "f"(v));
}
__device__ __forceinline__ void clusterSync() {
    asm volatile("barrier.cluster.arrive.aligned;" ::: "memory");
    asm volatile("barrier.cluster.wait.aligned;"   ::: "memory");
}
__device__ __forceinline__ float warpSum(float v) {
#pragma unroll
    for (int o = 16; o; o >>= 1) v += __shfl_down_sync(0xffffffffu, v, o);
    return v;
}
__device__ __forceinline__ float warpMax(float v) {
#pragma unroll
    for (int o = 16; o; o >>= 1) v = fmaxf(v, __shfl_down_sync(0xffffffffu, v, o));
    return v;
}

// ---------------- K1: Mexp = exp(sum_k w_k f_k) with boundary masks -------
__global__ void kM(const float* __restrict__ f, const float* __restrict__ w) {
    size_t lin = ((size_t)blockIdx.x * blockDim.x + threadIdx.x) * 4;
    float w0 = __ldg(w + 0), w1 = __ldg(w + 1), w2 = __ldg(w + 2), w3 = __ldg(w + 3);
    const float4 a = *(const float4*)(f + lin);
    const float4 b = *(const float4*)(f + lin + (size_t)MAT);
    const float4 c = *(const float4*)(f + lin + 2ull * MAT);
    const float4 d = *(const float4*)(f + lin + 3ull * MAT);
    int t  = (int)(lin >> 16);
    int i  = (int)(lin >> 8) & 255;
    int j0 = (int)lin & 255;
    float v0 = w0 * a.x + w1 * b.x + w2 * c.x + w3 * d.x;
    float v1 = w0 * a.y + w1 * b.y + w2 * c.y + w3 * d.y;
    float v2 = w0 * a.z + w1 * b.z + w2 * c.z + w3 * d.z;
    float v3 = w0 * a.w + w1 * b.w + w2 * c.w + w3 * d.w;
    bool mrow = (t == 0 && i != 0);
    float4 o;
    o.x = (mrow || (t == Tt && (j0 + 0) != 0)) ? 0.f : expf(v0);
    o.y = (mrow || (t == Tt && (j0 + 1) != 0)) ? 0.f : expf(v1);
    o.z = (mrow || (t == Tt && (j0 + 2) != 0)) ? 0.f : expf(v2);
    o.w = (mrow || (t == Tt && (j0 + 3) != 0)) ? 0.f : expf(v3);
    *(float4*)(g_Mexp + lin) = o;
}

// ---------------- K2: three scans, one cluster each -----------------------
// grid = 24 CTAs, cluster 8. cluster 0: forward, 1: backward, 2: viterbi.
__global__ void __cluster_dims__(8, 1, 1) __launch_bounds__(256, 1) kScan() {
    __shared__ float sInc[2][Yx];
    __shared__ float sPs[2][8];
    __shared__ float sCur[Yx];
    __shared__ float sRed[Yx];
    __shared__ int   sRedI[Yx];

    const int tid  = threadIdx.x;
    const int role = blockIdx.x >> 3;
    const int rank = blockIdx.x & 7;
    const int lane = tid & 31;
    const int wid  = tid >> 5;

    if (role == 0) {
        // ---------------- forward scan ----------------
        sCur[tid] = (tid == 0) ? 1.f : 0.f;
        if (tid < 32) g_alpha[32 * rank + tid] = (32 * rank + tid == 0) ? 1.f : 0.f;
        __syncthreads();
        const int col = 32 * rank + lane;
        const int ig  = wid;
        float m[32];
        {
            const float* bp = g_Mexp + (size_t)(ig * 32) * 256 + col;
#pragma unroll
            for (int k = 0; k < 32; k++) m[k] = bp[(size_t)k * 256];
        }
        int buf = 0;
        for (int t = 0; t < TP1; t++) {
            float acc = 0.f;
#pragma unroll
            for (int k = 0; k < 32; k++) acc += m[k] * sCur[ig * 32 + k];
            sRed[tid] = acc;
            __syncthreads();
            if (tid < 32) {
                float raw = 0.f;
#pragma unroll
                for (int g = 0; g < 8; g++) raw += sRed[g * 32 + tid];
                float ps = warpSum(raw);
                unsigned sa = smem_u32(&sInc[buf][32 * rank + tid]);
#pragma unroll
                for (int p = 0; p < 8; p++) stClusterF(sa, p, raw);
                if (tid == 0) {
                    unsigned pa = smem_u32(&sPs[buf][rank]);
#pragma unroll
                    for (int p = 0; p < 8; p++) stClusterF(pa, p, ps);
                }
            }
            if (t + 1 < TP1) { // prefetch next step's matrix slice (overlaps barrier)
                const float* bp = g_Mexp + (size_t)(t + 1) * 65536 + (size_t)(ig * 32) * 256 + col;
#pragma unroll
                for (int k = 0; k < 32; k++) m[k] = bp[(size_t)k * 256];
            }
            clusterSync();
            float s = 0.f;
#pragma unroll
            for (int p = 0; p < 8; p++) s += sPs[buf][p];
            float inv = 1.f / s;
            sCur[tid] = sInc[buf][tid] * inv;
            if (tid < 32)
                g_alpha[(size_t)(t + 1) * 256 + 32 * rank + tid] = sInc[buf][32 * rank + tid] * inv;
            if (rank == 0 && tid == 0) g_sA[t] = s;
            __syncthreads();
            buf ^= 1;
        }
    } else if (role == 1) {
        // ---------------- backward scan ----------------
        sCur[tid] = (tid == 0) ? 1.f : 0.f;
        if (tid < 32) g_beta[(size_t)513 * 256 + 32 * rank + tid] = (32 * rank + tid == 0) ? 1.f : 0.f;
        __syncthreads();
        const int rbase = 32 * rank + wid * 4;   // this warp owns rows rbase..rbase+3
        float m[32];
        {
            const float* bp = g_Mexp + (size_t)Tt * 65536 + (size_t)rbase * 256 + lane;
#pragma unroll
            for (int c = 0; c < 4; c++)
#pragma unroll
                for (int jb = 0; jb < 8; jb++) m[c * 8 + jb] = bp[(size_t)c * 256 + jb * 32];
        }
        int buf = 0;
        for (int t = Tt; t >= 0; t--) {
            float acc[4];
#pragma unroll
            for (int c = 0; c < 4; c++) {
                float a = 0.f;
#pragma unroll
                for (int jb = 0; jb < 8; jb++) a += m[c * 8 + jb] * sCur[jb * 32 + lane];
                acc[c] = warpSum(a);
            }
            if (lane == 0) {
#pragma unroll
                for (int c = 0; c < 4; c++) sRed[wid * 4 + c] = acc[c];
            }
            __syncthreads();
            if (tid < 32) {
                float raw = sRed[tid];
                float ps  = warpSum(raw);
                unsigned sa = smem_u32(&sInc[buf][32 * rank + tid]);
#pragma unroll
                for (int p = 0; p < 8; p++) stClusterF(sa, p, raw);
                if (tid == 0) {
                    unsigned pa = smem_u32(&sPs[buf][rank]);
#pragma unroll
                    for (int p = 0; p < 8; p++) stClusterF(pa, p, ps);
                }
            }
            if (t - 1 >= 0) {
                const float* bp = g_Mexp + (size_t)(t - 1) * 65536 + (size_t)rbase * 256 + lane;
#pragma unroll
                for (int c = 0; c < 4; c++)
#pragma unroll
                    for (int jb = 0; jb < 8; jb++) m[c * 8 + jb] = bp[(size_t)c * 256 + jb * 32];
            }
            clusterSync();
            float s = 0.f;
#pragma unroll
            for (int p = 0; p < 8; p++) s += sPs[buf][p];
            float inv = 1.f / s;
            sCur[tid] = sInc[buf][tid] * inv;
            if (tid < 32)
                g_beta[(size_t)t * 256 + 32 * rank + tid] = sInc[buf][32 * rank + tid] * inv;
            if (rank == 0 && tid == 0) g_sB[t] = s;
            __syncthreads();
            buf ^= 1;
        }
    } else {
        // ---------------- viterbi (max-times in linear space) ----------------
        float v = g_Mexp[tid];            // Mexp[0][0][tid]
        sRed[tid] = v;
        __syncthreads();
        if (tid < 32) {
            float mx = sRed[tid];
#pragma unroll
            for (int g = 1; g < 8; g++) mx = fmaxf(mx, sRed[g * 32 + tid]);
            mx = warpMax(mx);
            if (tid == 0) sPs[0][0] = mx;
        }
        __syncthreads();
        sCur[tid] = v / sPs[0][0];
        __syncthreads();

        const int col = 32 * rank + lane;
        const int ig  = wid;
        float m[32];
        {
            const float* bp = g_Mexp + (size_t)65536 + (size_t)(ig * 32) * 256 + col;
#pragma unroll
            for (int k = 0; k < 32; k++) m[k] = bp[(size_t)k * 256];
        }
        int buf = 0;
        for (int t = 1; t < Tt; t++) {
            float best = -1.f; int bi = 0;
#pragma unroll
            for (int k = 0; k < 32; k++) {
                float p = m[k] * sCur[ig * 32 + k];
                if (p > best) { best = p; bi = ig * 32 + k; }   // strict > keeps lowest i
            }
            sRed[tid] = best; sRedI[tid] = bi;
            __syncthreads();
            if (tid < 32) {
                float bv = sRed[tid]; int bix = sRedI[tid];
#pragma unroll
                for (int g = 1; g < 8; g++) {
                    float vv = sRed[g * 32 + tid];
                    if (vv > bv) { bv = vv; bix = sRedI[g * 32 + tid]; }
                }
                g_idx[(size_t)(t - 1) * 256 + 32 * rank + tid] = (unsigned char)bix;
                float pm = warpMax(bv);
                unsigned sa = smem_u32(&sInc[buf][32 * rank + tid]);
#pragma unroll
                for (int p = 0; p < 8; p++) stClusterF(sa, p, bv);
                if (tid == 0) {
                    unsigned pa = smem_u32(&sPs[buf][rank]);
#pragma unroll
                    for (int p = 0; p < 8; p++) stClusterF(pa, p, pm);
                }
            }
            if (t + 1 < Tt) {
                const float* bp = g_Mexp + (size_t)(t + 1) * 65536 + (size_t)(ig * 32) * 256 + col;
#pragma unroll
                for (int k = 0; k < 32; k++) m[k] = bp[(size_t)k * 256];
            }
            clusterSync();
            float s = sPs[buf][0];
#pragma unroll
            for (int p = 1; p < 8; p++) s = fmaxf(s, sPs[buf][p]);
            sCur[tid] = sInc[buf][tid] / s;   // uniform scale: argmax preserved
            __syncthreads();
            buf ^= 1;
        }
        if (rank == 0) g_dfin[tid] = sCur[tid];
    }
}

// ---------------- K3: log-scale prefix sums (double), Ap, backtrack -------
extern __shared__ unsigned char sdyn[];
__global__ void kFinish(float* __restrict__ dout, int writePath) {
    double* sLA = (double*)sdyn;                 // [514]
    double* sLB = sLA + 514;                     // [514]
    unsigned char* sIdx = (unsigned char*)(sLB + 514); // [511*256]
    int tid = threadIdx.x;

    { // stage backpointers into smem (coalesced)
        const uint4* src = (const uint4*)g_idx;
        uint4* dst = (uint4*)sIdx;
        for (int i = tid; i < (511 * 256) / 16; i += 256) dst[i] = src[i];
    }
    for (int t = tid; t < 513; t += 256) {
        sLA[t + 1] = log((double)g_sA[t]);
        sLB[t]     = log((double)g_sB[t]);
    }
    if (tid == 0) { sLA[0] = 0.0; sLB[513] = 0.0; }
    __syncthreads();
    if (tid == 0) {            // LA prefix sum
        double r = 0.0;
        for (int t = 1; t <= 513; t++) { r += sLA[t]; sLA[t] = r; }
    } else if (tid == 32) {    // LB suffix sum
        double r = 0.0;
        for (int t = 512; t >= 0; t--) { r += sLB[t]; sLB[t] = r; }
    } else if (tid == 64 && writePath) {  // backtrack (parallel with prefix sums)
        float best = g_dfin[0]; int last = 0;
        for (int j = 1; j < 256; j++) { float v = g_dfin[j]; if (v > best) { best = v; last = j; } }
        float* pout = dout + (size_t)MAT;
        pout[511] = (float)last;
        int y = last;
        for (int r = 510; r >= 0; r--) { y = sIdx[r * 256 + y]; pout[r] = (float)y; }
    }
    __syncthreads();
    double lz = sLA[513];
    for (int t = 0; t < 513; t++) {
        float Fv = expf((float)(sLA[t] + sLB[t + 1] - lz));
        g_Ap[t * 256 + tid] = g_alpha[t * 256 + tid] * Fv;
    }
}

// ---------------- K4: p12 = Ap[t][i] * Mexp * beta[t+1][j] ----------------
__global__ void kP12(float* __restrict__ dout) {
    size_t lin = ((size_t)blockIdx.x * blockDim.x + threadIdx.x) * 4;
    int t = (int)(lin >> 16);
    int i = (int)(lin >> 8) & 255;
    int j = (int)lin & 255;
    float4 mv = *(const float4*)(g_Mexp + lin);
    float  a  = g_Ap[t * 256 + i];
    float4 bv = *(const float4*)(g_beta + (size_t)(t + 1) * 256 + j);
    float4 o;
    o.x = a * mv.x * bv.x;
    o.y = a * mv.y * bv.y;
    o.z = a * mv.z * bv.z;
    o.w = a * mv.w * bv.w;
    *(float4*)(dout + lin) = o;
}

// ---------------- launch ---------------------------------------------------
extern "C" void kernel_launch(void* const* d_in, const int* in_sizes, int n_in,
                              void* d_out, int out_size) {
    const float* f = (const float*)d_in[0];
    const float* w = (const float*)d_in[1];
    if (n_in >= 2 && in_sizes[0] == 4) {  // defensive: order f,w vs w,f
        f = (const float*)d_in[1];
        w = (const float*)d_in[0];
    }
    float* out = (float*)d_out;
    int writePath = (out_size >= MAT + 512) ? 1 : 0;

    const int FIN_SMEM = 514 * 8 * 2 + 511 * 256;  // 139,040 B
    cudaFuncSetAttribute(kFinish, cudaFuncAttributeMaxDynamicSharedMemorySize, FIN_SMEM);

    kM<<<32832, 256>>>(f, w);            // 33,619,968 / (256*4)
    kScan<<<24, 256>>>();                // 3 clusters of 8
    kFinish<<<1, 256, FIN_SMEM>>>(out, writePath);
    kP12<<<32832, 256>>>(out);
}